// round 6
// baseline (speedup 1.0000x reference)
#include <cuda_runtime.h>
#include <cuda_fp16.h>
#include <math.h>
#include <stdint.h>

// ---------------------------------------------------------------------------
#define THREADS   256
#define MPB       128            // points per block
// k-permutation within each 16-group: pairs (2t,2t+1,2t+8,2t+9) contiguous
__host__ __device__ __forceinline__ int perm16(int k) {
    return ((k >> 1) & 3) * 4 + (k & 1) + ((k >> 3) & 1) * 2;
}
__host__ __device__ __forceinline__ int permpos(int k) {
    return (k & ~15) + perm16(k & 15);
}

// smem byte offsets
#define PX        528u           // X row pitch (256 halves + pad)
#define PW        144u           // W row pitch (72 halves)
#define X_PLANE   67584u         // 128 * PX
#define OFF_X1    0u
#define OFF_X2    67584u
#define OFF_WA    135168u        // W buffer A (36864B)
#define OFF_WB    172032u        // W buffer B
#define OFF_BIAS  208896u        // 2053 floats (pad 8224)
#define OFF_PART  217120u        // 128*4 floats
#define OFF_OCC   219168u        // 128*2 floats
#define SMEM_TOTAL 220192u

#define SB_B0   0
#define SB_B1   256
#define SB_B2   512
#define SB_WOCC 768
#define SB_WC   1024
#define SB_BC   2048
#define SB_BOCC 2052

// ---------------------------------------------------------------------------
// prepped fp16 weight images (smem-image layout, flat cp.async copy)
__device__ __align__(16) __half g_W0[256 * 72];
__device__ __align__(16) __half g_W1[4][256 * 72];
__device__ __align__(16) __half g_W2[4][256 * 72];

// ---------------------------------------------------------------------------
__device__ __forceinline__ uint32_t smem_u32(const void* p) {
    uint32_t a;
    asm("{ .reg .u64 t; cvta.to.shared.u64 t, %1; cvt.u32.u64 %0, t; }" : "=r"(a) : "l"(p));
    return a;
}
__device__ __forceinline__ void lds64(uint32_t addr, uint32_t& x, uint32_t& y) {
    asm volatile("ld.shared.v2.b32 {%0,%1}, [%2];" : "=r"(x), "=r"(y) : "r"(addr));
}
__device__ __forceinline__ void mma16816(float* c, uint32_t a0, uint32_t a1,
                                         uint32_t a2, uint32_t a3,
                                         uint32_t b0, uint32_t b1) {
    asm volatile(
        "mma.sync.aligned.m16n8k16.row.col.f32.f16.f16.f32 "
        "{%0,%1,%2,%3}, {%4,%5,%6,%7}, {%8,%9}, {%0,%1,%2,%3};"
        : "+f"(c[0]), "+f"(c[1]), "+f"(c[2]), "+f"(c[3])
        : "r"(a0), "r"(a1), "r"(a2), "r"(a3), "r"(b0), "r"(b1));
}
__device__ __forceinline__ void hsplit(float v, uint16_t& h, uint16_t& l) {
    __half hh = __float2half_rn(v);
    __half ll = __float2half_rn(v - __half2float(hh));
    h = __half_as_ushort(hh);
    l = __half_as_ushort(ll);
}
__device__ __forceinline__ void cp16(uint32_t dst, const void* src) {
    asm volatile("cp.async.cg.shared.global [%0], [%1], 16;" :: "r"(dst), "l"(src));
}
#define CP_COMMIT() asm volatile("cp.async.commit_group;")
#define CP_WAIT0()  asm volatile("cp.async.wait_group 0;" ::: "memory")

__device__ __forceinline__ void stage_async(uint32_t dst, const __half* src, int t) {
    const char* s = (const char*)src;
    #pragma unroll
    for (int r = 0; r < 9; r++) {
        int i = (t + 256 * r) * 16;
        cp16(dst + i, s + i);
    }
    CP_COMMIT();
}

// ---------------------------------------------------------------------------
__global__ void prep_kernel(const float* __restrict__ W0,
                            const float* __restrict__ W1,
                            const float* __restrict__ W2)
{
    int i = blockIdx.x * THREADS + threadIdx.x;     // 147456 total
    float v; __half* d; int dst;
    if (i < 16384) {                                 // W0^T
        int n = i >> 6, kl = i & 63;
        v = (kl < 63) ? W0[kl * 256 + n] : 0.f;
        dst = n * 72 + permpos(kl);
        d = g_W0;
    } else if (i < 16384 + 65536) {                  // W1^T
        int t2 = i - 16384;
        int c = t2 >> 14, n = (t2 >> 6) & 255, kl = t2 & 63;
        v = W1[(c * 64 + kl) * 256 + n];
        dst = n * 72 + permpos(kl);
        d = g_W1[c];
    } else {                                         // W2^T
        int t2 = i - 16384 - 65536;
        if (t2 >= 65536) return;
        int c = t2 >> 14, n = (t2 >> 6) & 255, kl = t2 & 63;
        v = W2[(c * 64 + kl) * 256 + n];
        dst = n * 72 + permpos(kl);
        d = g_W2[c];
    }
    d[dst] = __float2half_rn(v);
}

// ---------------------------------------------------------------------------
// one 64-k chunk of 2-term fp16 MMA over 32m x 128n warp tile
__device__ __forceinline__ void mma_chunk(float acc[2][16][4],
                                          uint32_t abase, uint32_t wbase)
{
    #pragma unroll
    for (int kt = 0; kt < 4; kt++) {
        uint32_t ah[2][4], al[2][4];
        #pragma unroll
        for (int mt = 0; mt < 2; mt++) {
            uint32_t base = abase + mt * (16 * PX) + kt * 32;
            lds64(base,                    ah[mt][0], ah[mt][2]);
            lds64(base + 8 * PX,           ah[mt][1], ah[mt][3]);
            lds64(base + X_PLANE,          al[mt][0], al[mt][2]);
            lds64(base + 8 * PX + X_PLANE, al[mt][1], al[mt][3]);
        }
        uint32_t wb = wbase + kt * 32;
        #pragma unroll
        for (int nt = 0; nt < 16; nt++) {
            uint32_t b0, b1;
            lds64(wb, b0, b1);
            wb += 8 * PW;
            #pragma unroll
            for (int mt = 0; mt < 2; mt++) {
                mma16816(acc[mt][nt], ah[mt][0], ah[mt][1], ah[mt][2], ah[mt][3], b0, b1);
                mma16816(acc[mt][nt], al[mt][0], al[mt][1], al[mt][2], al[mt][3], b0, b1);
            }
        }
    }
}

// ---------------------------------------------------------------------------
__global__ __launch_bounds__(THREADS, 1)
void mlp3d_mma(const float* __restrict__ coords,
               const float* __restrict__ b0, const float* __restrict__ b1,
               const float* __restrict__ b2,
               const float* __restrict__ Wocc, const float* __restrict__ bocc,
               const float* __restrict__ Wc, const float* __restrict__ bc,
               float* __restrict__ out, int npts)
{
    extern __shared__ char sm[];
    char*  sx1 = sm + OFF_X1;
    char*  sx2 = sm + OFF_X2;
    float* s_bias = (float*)(sm + OFF_BIAS);
    float* s_part = (float*)(sm + OFF_PART);   // [m][p]
    float* s_occ  = (float*)(sm + OFF_OCC);    // [m][ns]
    const uint32_t smb = smem_u32(sm);
    const uint32_t wbuf[2] = { smb + OFF_WA, smb + OFF_WB };

    const int t = threadIdx.x;
    const int warp = t >> 5, lane = t & 31;
    const int ms = warp & 3;            // rows 32ms..+31
    const int ns = warp >> 2;           // cols 128ns..+127
    const int g = lane >> 2, tg = lane & 3;
    const int gbase = blockIdx.x * MPB;

    const uint32_t abase = smb + OFF_X1 + (uint32_t)(32 * ms + g) * PX + 8 * tg;
    const uint32_t wmain_off = (uint32_t)(128 * ns + g) * PW + 8 * tg;

    // ---- prefetch W0 via cp.async (no regs, hides under embedding) ----
    stage_async(wbuf[0], g_W0, t);

    // ---- biases/heads -> smem ----
    for (int i = t; i < 2053; i += THREADS) {
        float v;
        if      (i < 256)  v = b0[i];
        else if (i < 512)  v = b1[i - 256];
        else if (i < 768)  v = b2[i - 512];
        else if (i < 1024) v = Wocc[i - 768];
        else if (i < 2048) v = Wc[i - 1024];
        else if (i < 2052) v = bc[i - 2048];
        else               v = bocc[0];
        s_bias[i] = v;
    }

    // ---- embedding -> X chunk0 (k-permuted, hi/lo fp16 planes) ----
    for (int task = t; task < 384; task += THREADS) {
        int pt = task & 127, d = task >> 7;
        int eg = gbase + pt;
        float v = (eg < npts) ? coords[eg * 3 + d] : 0.f;
        char* r1 = sx1 + pt * PX;
        char* r2 = sx2 + pt * PX;
        uint16_t hh, ll;
        hsplit(v, hh, ll);
        int p0 = permpos(d);
        *(uint16_t*)(r1 + 2 * p0) = hh; *(uint16_t*)(r2 + 2 * p0) = ll;
        float f = 1.f;
        #pragma unroll
        for (int fr = 0; fr < 10; fr++) {
            float sv, cv;
            sincosf(v * f, &sv, &cv);
            int ps = permpos(3 + fr * 6 + d);
            int pc = permpos(6 + fr * 6 + d);
            hsplit(sv, hh, ll);
            *(uint16_t*)(r1 + 2 * ps) = hh; *(uint16_t*)(r2 + 2 * ps) = ll;
            hsplit(cv, hh, ll);
            *(uint16_t*)(r1 + 2 * pc) = hh; *(uint16_t*)(r2 + 2 * pc) = ll;
            f *= 2.f;
        }
    }
    if (t < 128) {   // pad k=63
        *(uint16_t*)(sx1 + t * PX + 2 * 63) = 0;
        *(uint16_t*)(sx2 + t * PX + 2 * 63) = 0;
    }
    CP_WAIT0();
    __syncthreads();

    float acc[2][16][4];

    // ================= layer 0 ==============================================
    stage_async(wbuf[1], g_W1[0], t);
    #pragma unroll
    for (int mt = 0; mt < 2; mt++)
        #pragma unroll
        for (int nt = 0; nt < 16; nt++)
            #pragma unroll
            for (int u = 0; u < 4; u++) acc[mt][nt][u] = 0.f;
    mma_chunk(acc, abase, wbuf[0] + wmain_off);
    __syncthreads();                 // emb + W0 reads done

    // epi L0: x = acc + b0 -> X
    #pragma unroll
    for (int mt = 0; mt < 2; mt++) {
        int r0 = 32 * ms + 16 * mt + g;
        #pragma unroll
        for (int nt = 0; nt < 16; nt++) {
            int j0 = 128 * ns + 8 * nt + 2 * tg;
            int kp = (j0 & ~15) * 2 + perm16(j0 & 15) * 2;
            float bb0 = s_bias[SB_B0 + j0], bb1 = s_bias[SB_B0 + j0 + 1];
            uint16_t h0, l0, h1, l1;
            hsplit(acc[mt][nt][0] + bb0, h0, l0);
            hsplit(acc[mt][nt][1] + bb1, h1, l1);
            *(uint32_t*)(sx1 + r0 * PX + kp) = (uint32_t)h0 | ((uint32_t)h1 << 16);
            *(uint32_t*)(sx2 + r0 * PX + kp) = (uint32_t)l0 | ((uint32_t)l1 << 16);
            hsplit(acc[mt][nt][2] + bb0, h0, l0);
            hsplit(acc[mt][nt][3] + bb1, h1, l1);
            *(uint32_t*)(sx1 + (r0 + 8) * PX + kp) = (uint32_t)h0 | ((uint32_t)h1 << 16);
            *(uint32_t*)(sx2 + (r0 + 8) * PX + kp) = (uint32_t)l0 | ((uint32_t)l1 << 16);
        }
    }
    CP_WAIT0();
    __syncthreads();

    // ================= layer 1 (+ part heads via chunk-delta) ===============
    #pragma unroll
    for (int mt = 0; mt < 2; mt++)
        #pragma unroll
        for (int nt = 0; nt < 16; nt++)
            #pragma unroll
            for (int u = 0; u < 4; u++) acc[mt][nt][u] = 0.f;

    float pcls[2][2][2];             // [local part][mt][row half]
    #pragma unroll
    for (int a = 0; a < 2; a++)
        #pragma unroll
        for (int b = 0; b < 2; b++)
            #pragma unroll
            for (int cc = 0; cc < 2; cc++) pcls[a][b][cc] = 0.f;

    #pragma unroll
    for (int c = 0; c < 4; c++) {
        const uint32_t cur = wbuf[(1 + c) & 1];
        const uint32_t other = wbuf[c & 1];
        stage_async(other, (c < 3) ? g_W1[c + 1] : g_W2[0], t);

        const bool mine = (ns == (c >> 1));
        const int local = c & 1, nt0 = 8 * local;
        float snap[2][8][4];
        if (mine) {
            #pragma unroll
            for (int mt = 0; mt < 2; mt++)
                #pragma unroll
                for (int j = 0; j < 8; j++)
                    #pragma unroll
                    for (int u = 0; u < 4; u++) snap[mt][j][u] = acc[mt][nt0 + j][u];
        }

        mma_chunk(acc, abase + c * 128, cur + wmain_off);

        if (mine) {
            const int p = c;
            #pragma unroll
            for (int mt = 0; mt < 2; mt++)
                #pragma unroll
                for (int j = 0; j < 8; j++) {
                    int jc = 128 * ns + 8 * (nt0 + j) + 2 * tg;
                    float bb0 = s_bias[SB_B1 + jc], bb1 = s_bias[SB_B1 + jc + 1];
                    float wc0 = s_bias[SB_WC + p * 256 + jc];
                    float wc1 = s_bias[SB_WC + p * 256 + jc + 1];
                    float d0 = acc[mt][nt0 + j][0] - snap[mt][j][0] + bb0;
                    float d1 = acc[mt][nt0 + j][1] - snap[mt][j][1] + bb1;
                    float d2 = acc[mt][nt0 + j][2] - snap[mt][j][2] + bb0;
                    float d3 = acc[mt][nt0 + j][3] - snap[mt][j][3] + bb1;
                    pcls[local][mt][0] = fmaf(fmaxf(d0, 0.f), wc0, pcls[local][mt][0]);
                    pcls[local][mt][0] = fmaf(fmaxf(d1, 0.f), wc1, pcls[local][mt][0]);
                    pcls[local][mt][1] = fmaf(fmaxf(d2, 0.f), wc0, pcls[local][mt][1]);
                    pcls[local][mt][1] = fmaf(fmaxf(d3, 0.f), wc1, pcls[local][mt][1]);
                }
        }
        CP_WAIT0();
        __syncthreads();
    }

    // part head reduce over tg, write s_part
    #pragma unroll
    for (int local = 0; local < 2; local++)
        #pragma unroll
        for (int mt = 0; mt < 2; mt++)
            #pragma unroll
            for (int hh = 0; hh < 2; hh++) {
                float v = pcls[local][mt][hh];
                v += __shfl_xor_sync(0xffffffffu, v, 1);
                v += __shfl_xor_sync(0xffffffffu, v, 2);
                if (tg == 0) {
                    int r = 32 * ms + 16 * mt + g + 8 * hh;
                    s_part[r * 4 + 2 * ns + local] = v;
                }
            }

    // epi L1: y = relu(acc + b1) -> X
    #pragma unroll
    for (int mt = 0; mt < 2; mt++) {
        int r0 = 32 * ms + 16 * mt + g;
        #pragma unroll
        for (int nt = 0; nt < 16; nt++) {
            int j0 = 128 * ns + 8 * nt + 2 * tg;
            int kp = (j0 & ~15) * 2 + perm16(j0 & 15) * 2;
            float bb0 = s_bias[SB_B1 + j0], bb1 = s_bias[SB_B1 + j0 + 1];
            uint16_t h0, l0, h1, l1;
            hsplit(fmaxf(acc[mt][nt][0] + bb0, 0.f), h0, l0);
            hsplit(fmaxf(acc[mt][nt][1] + bb1, 0.f), h1, l1);
            *(uint32_t*)(sx1 + r0 * PX + kp) = (uint32_t)h0 | ((uint32_t)h1 << 16);
            *(uint32_t*)(sx2 + r0 * PX + kp) = (uint32_t)l0 | ((uint32_t)l1 << 16);
            hsplit(fmaxf(acc[mt][nt][2] + bb0, 0.f), h0, l0);
            hsplit(fmaxf(acc[mt][nt][3] + bb1, 0.f), h1, l1);
            *(uint32_t*)(sx1 + (r0 + 8) * PX + kp) = (uint32_t)h0 | ((uint32_t)h1 << 16);
            *(uint32_t*)(sx2 + (r0 + 8) * PX + kp) = (uint32_t)l0 | ((uint32_t)l1 << 16);
        }
    }
    __syncthreads();

    // ================= layer 2 =============================================
    #pragma unroll
    for (int mt = 0; mt < 2; mt++)
        #pragma unroll
        for (int nt = 0; nt < 16; nt++)
            #pragma unroll
            for (int u = 0; u < 4; u++) acc[mt][nt][u] = 0.f;

    #pragma unroll
    for (int c = 0; c < 4; c++) {
        const uint32_t cur = wbuf[(1 + c) & 1];
        const uint32_t other = wbuf[c & 1];
        if (c < 3) stage_async(other, g_W2[c + 1], t);
        mma_chunk(acc, abase + c * 128, cur + wmain_off);
        CP_WAIT0();
        __syncthreads();
    }

    // ---- occ head ----
    {
        float rs[2][2] = {{0.f, 0.f}, {0.f, 0.f}};
        #pragma unroll
        for (int mt = 0; mt < 2; mt++)
            #pragma unroll
            for (int nt = 0; nt < 16; nt++) {
                int j0 = 128 * ns + 8 * nt + 2 * tg;
                float bb0 = s_bias[SB_B2 + j0], bb1 = s_bias[SB_B2 + j0 + 1];
                float wo0 = s_bias[SB_WOCC + j0], wo1 = s_bias[SB_WOCC + j0 + 1];
                rs[mt][0] = fmaf(fmaxf(acc[mt][nt][0] + bb0, 0.f), wo0, rs[mt][0]);
                rs[mt][0] = fmaf(fmaxf(acc[mt][nt][1] + bb1, 0.f), wo1, rs[mt][0]);
                rs[mt][1] = fmaf(fmaxf(acc[mt][nt][2] + bb0, 0.f), wo0, rs[mt][1]);
                rs[mt][1] = fmaf(fmaxf(acc[mt][nt][3] + bb1, 0.f), wo1, rs[mt][1]);
            }
        #pragma unroll
        for (int mt = 0; mt < 2; mt++)
            #pragma unroll
            for (int hh = 0; hh < 2; hh++) {
                float v = rs[mt][hh];
                v += __shfl_xor_sync(0xffffffffu, v, 1);
                v += __shfl_xor_sync(0xffffffffu, v, 2);
                if (tg == 0) {
                    int r = 32 * ms + 16 * mt + g + 8 * hh;
                    s_occ[r * 2 + ns] = v;
                }
            }
    }
    __syncthreads();

    // ---- final stores ----
    if (t < 128) {
        int gm = gbase + t;
        if (gm < npts)
            out[gm] = s_occ[2 * t] + s_occ[2 * t + 1] + s_bias[SB_BOCC];
    }
    #pragma unroll
    for (int it = 0; it < 2; it++) {
        int idx = t + it * THREADS;
        int m = idx >> 2, p = idx & 3;
        int gm = gbase + m;
        if (gm < npts)
            out[npts + gm * 4 + p] = s_part[m * 4 + p] + s_bias[SB_BC + p];
    }
}

// ---------------------------------------------------------------------------
extern "C" void kernel_launch(void* const* d_in, const int* in_sizes, int n_in,
                              void* d_out, int out_size)
{
    const float* coords = (const float*)d_in[0];
    const float* W0   = (const float*)d_in[1];
    const float* b0   = (const float*)d_in[2];
    const float* W1   = (const float*)d_in[3];
    const float* b1   = (const float*)d_in[4];
    const float* W2   = (const float*)d_in[5];
    const float* b2   = (const float*)d_in[6];
    const float* Wocc = (const float*)d_in[7];
    const float* bocc = (const float*)d_in[8];
    const float* Wc   = (const float*)d_in[9];
    const float* bc   = (const float*)d_in[10];
    float* out = (float*)d_out;

    int npts = in_sizes[0] / 3;
    int blocks = (npts + MPB - 1) / MPB;

    prep_kernel<<<576, THREADS>>>(W0, W1, W2);

    cudaFuncSetAttribute(mlp3d_mma, cudaFuncAttributeMaxDynamicSharedMemorySize,
                         (int)SMEM_TOTAL);
    mlp3d_mma<<<blocks, THREADS, SMEM_TOTAL>>>(coords, b0, b1, b2, Wocc, bocc,
                                               Wc, bc, out, npts);
    (void)n_in; (void)out_size;
}

// round 7
// speedup vs baseline: 1.2954x; 1.2954x over previous
#include <cuda_runtime.h>
#include <cuda_fp16.h>
#include <math.h>
#include <stdint.h>

// ---------------------------------------------------------------------------
#define THREADS   512
#define MPB       128
// k-permutation within each 16-group: pairs (2t,2t+1,2t+8,2t+9) contiguous
__host__ __device__ __forceinline__ int perm16(int k) {
    return ((k >> 1) & 3) * 4 + (k & 1) + ((k >> 3) & 1) * 2;
}

// smem layout (bytes). X plane: [ktg 16][m 128][32B] = 65536. W image: [kt 4][n 256][32B] = 32768.
#define X_PLANE   65536u
#define OFF_X1    0u
#define OFF_X2    65536u
#define OFF_WA    131072u
#define OFF_WB    163840u
#define OFF_BIAS  196608u        // 2053 floats -> 8224B
#define OFF_PART  204832u        // 128*4*4 floats = 8192B  [m][p][ns]
#define OFF_OCC   213024u        // 128*4 floats = 2048B    [m][ns]
#define SMEM_TOTAL 215072u

#define SB_B0   0
#define SB_B1   256
#define SB_B2   512
#define SB_WOCC 768
#define SB_WC   1024
#define SB_BC   2048
#define SB_BOCC 2052

// ---------------------------------------------------------------------------
// prepped fp16 weight images: [kt 4][n 256][16 halves], flat cp.async copy
__device__ __align__(16) __half g_W0[16384];
__device__ __align__(16) __half g_W1[4][16384];
__device__ __align__(16) __half g_W2[4][16384];

// ---------------------------------------------------------------------------
__device__ __forceinline__ uint32_t smem_u32(const void* p) {
    uint32_t a;
    asm("{ .reg .u64 t; cvta.to.shared.u64 t, %1; cvt.u32.u64 %0, t; }" : "=r"(a) : "l"(p));
    return a;
}
__device__ __forceinline__ void lds64(uint32_t addr, uint32_t& x, uint32_t& y) {
    asm volatile("ld.shared.v2.b32 {%0,%1}, [%2];" : "=r"(x), "=r"(y) : "r"(addr));
}
__device__ __forceinline__ void mma16816(float* c, uint32_t a0, uint32_t a1,
                                         uint32_t a2, uint32_t a3,
                                         uint32_t b0, uint32_t b1) {
    asm volatile(
        "mma.sync.aligned.m16n8k16.row.col.f32.f16.f16.f32 "
        "{%0,%1,%2,%3}, {%4,%5,%6,%7}, {%8,%9}, {%0,%1,%2,%3};"
        : "+f"(c[0]), "+f"(c[1]), "+f"(c[2]), "+f"(c[3])
        : "r"(a0), "r"(a1), "r"(a2), "r"(a3), "r"(b0), "r"(b1));
}
__device__ __forceinline__ void hsplit(float v, uint16_t& h, uint16_t& l) {
    __half hh = __float2half_rn(v);
    __half ll = __float2half_rn(v - __half2float(hh));
    h = __half_as_ushort(hh);
    l = __half_as_ushort(ll);
}
__device__ __forceinline__ void cp16(uint32_t dst, const void* src) {
    asm volatile("cp.async.cg.shared.global [%0], [%1], 16;" :: "r"(dst), "l"(src));
}
#define CP_COMMIT() asm volatile("cp.async.commit_group;")
#define CP_WAIT0()  asm volatile("cp.async.wait_group 0;" ::: "memory")

// stage a 32768B weight image
__device__ __forceinline__ void stage_async(uint32_t dst, const __half* src, int t) {
    const char* s = (const char*)src;
    #pragma unroll
    for (int r = 0; r < 4; r++) {
        int i = (t + 512 * r) * 16;
        cp16(dst + i, s + i);
    }
    CP_COMMIT();
}

// ---------------------------------------------------------------------------
__global__ void prep_kernel(const float* __restrict__ W0,
                            const float* __restrict__ W1,
                            const float* __restrict__ W2)
{
    int i = blockIdx.x * 256 + threadIdx.x;          // 147456 total
    float v; __half* d; int n, kl;
    if (i < 16384) {                                  // W0^T
        n = i >> 6; kl = i & 63;
        v = (kl < 63) ? W0[kl * 256 + n] : 0.f;
        d = g_W0;
    } else if (i < 16384 + 65536) {                   // W1^T
        int t2 = i - 16384;
        int c = t2 >> 14; n = (t2 >> 6) & 255; kl = t2 & 63;
        v = W1[(c * 64 + kl) * 256 + n];
        d = g_W1[c];
    } else {                                          // W2^T
        int t2 = i - 16384 - 65536;
        if (t2 >= 65536) return;
        int c = t2 >> 14; n = (t2 >> 6) & 255; kl = t2 & 63;
        v = W2[(c * 64 + kl) * 256 + n];
        d = g_W2[c];
    }
    int kt = kl >> 4, pp = perm16(kl & 15);
    d[kt * 4096 + n * 16 + pp] = __float2half_rn(v);
}

// ---------------------------------------------------------------------------
// one 64-k chunk of 2-term fp16 MMA over 32m x 64n warp tile.
// a_base: smb+OFF_X1 + chunk*16384 + (32ms+g)*32 + 8tg ; w_base: cur + (64ns+g)*32 + 8tg
template<int NNT>
__device__ __forceinline__ void mma_chunk(float acc[2][NNT][4],
                                          uint32_t a_base, uint32_t w_base)
{
    #pragma unroll
    for (int kt = 0; kt < 4; kt++) {
        uint32_t ah[2][4], al[2][4];
        #pragma unroll
        for (int mt = 0; mt < 2; mt++) {
            uint32_t base = a_base + kt * 4096 + mt * 512;
            lds64(base,                ah[mt][0], ah[mt][2]);
            lds64(base + 256,          ah[mt][1], ah[mt][3]);
            lds64(base + X_PLANE,      al[mt][0], al[mt][2]);
            lds64(base + 256 + X_PLANE, al[mt][1], al[mt][3]);
        }
        uint32_t wb = w_base + kt * 8192;
        #pragma unroll
        for (int nt = 0; nt < NNT; nt++) {
            uint32_t b0, b1;
            lds64(wb, b0, b1);
            wb += 256;
            #pragma unroll
            for (int mt = 0; mt < 2; mt++) {
                mma16816(acc[mt][nt], ah[mt][0], ah[mt][1], ah[mt][2], ah[mt][3], b0, b1);
                mma16816(acc[mt][nt], al[mt][0], al[mt][1], al[mt][2], al[mt][3], b0, b1);
            }
        }
    }
}

// ---------------------------------------------------------------------------
__global__ __launch_bounds__(THREADS, 1)
void mlp3d_mma(const float* __restrict__ coords,
               const float* __restrict__ b0, const float* __restrict__ b1,
               const float* __restrict__ b2,
               const float* __restrict__ Wocc, const float* __restrict__ bocc,
               const float* __restrict__ Wc, const float* __restrict__ bc,
               float* __restrict__ out, int npts)
{
    extern __shared__ char sm[];
    char*  sx1 = sm + OFF_X1;
    char*  sx2 = sm + OFF_X2;
    float* s_bias = (float*)(sm + OFF_BIAS);
    float* s_part = (float*)(sm + OFF_PART);   // [m][p][ns]
    float* s_occ  = (float*)(sm + OFF_OCC);    // [m][ns]
    const uint32_t smb = smem_u32(sm);
    const uint32_t wbuf[2] = { smb + OFF_WA, smb + OFF_WB };

    const int t = threadIdx.x;
    const int warp = t >> 5, lane = t & 31;
    const int ms = warp & 3;            // rows 32ms..+31
    const int ns = warp >> 2;           // cols 64ns..+63 (4 strips)
    const int g = lane >> 2, tg = lane & 3;
    const int gbase = blockIdx.x * MPB;

    const uint32_t a_base = smb + OFF_X1 + (uint32_t)(32 * ms + g) * 32 + 8 * tg;
    const uint32_t w_row  = (uint32_t)(64 * ns + g) * 32 + 8 * tg;

    // ---- stage W0, biases, embedding ----
    stage_async(wbuf[0], g_W0, t);

    for (int i = t; i < 2053; i += THREADS) {
        float v;
        if      (i < 256)  v = b0[i];
        else if (i < 512)  v = b1[i - 256];
        else if (i < 768)  v = b2[i - 512];
        else if (i < 1024) v = Wocc[i - 768];
        else if (i < 2048) v = Wc[i - 1024];
        else if (i < 2052) v = bc[i - 2048];
        else               v = bocc[0];
        s_bias[i] = v;
    }

    // embedding -> X chunk 0 ([ktg][m][32B] layout, hi/lo planes)
    if (t < 384) {
        int pt = t & 127, d = t >> 7;
        int eg = gbase + pt;
        float v = (eg < npts) ? coords[eg * 3 + d] : 0.f;
        uint16_t hh, ll;
        hsplit(v, hh, ll);
        int k = d, ktg = k >> 4, pp = perm16(k & 15);
        uint32_t off = ktg * 4096u + pt * 32u + pp * 2u;
        *(uint16_t*)(sx1 + off) = hh; *(uint16_t*)(sx2 + off) = ll;
        float f = 1.f;
        #pragma unroll
        for (int fr = 0; fr < 10; fr++) {
            float sv, cv;
            sincosf(v * f, &sv, &cv);
            int ks = 3 + fr * 6 + d, kc = ks + 3;
            uint32_t os = (ks >> 4) * 4096u + pt * 32u + perm16(ks & 15) * 2u;
            uint32_t oc = (kc >> 4) * 4096u + pt * 32u + perm16(kc & 15) * 2u;
            hsplit(sv, hh, ll);
            *(uint16_t*)(sx1 + os) = hh; *(uint16_t*)(sx2 + os) = ll;
            hsplit(cv, hh, ll);
            *(uint16_t*)(sx1 + oc) = hh; *(uint16_t*)(sx2 + oc) = ll;
            f *= 2.f;
        }
    }
    if (t < 128) {   // pad k=63: ktg=3, pp=perm16(15)=15
        uint32_t off = 3 * 4096u + t * 32u + 15 * 2u;
        *(uint16_t*)(sx1 + off) = 0;
        *(uint16_t*)(sx2 + off) = 0;
    }
    CP_WAIT0();
    __syncthreads();

    float acc[2][8][4];

    // ================= layer 0 ==============================================
    stage_async(wbuf[1], g_W1[0], t);
    #pragma unroll
    for (int mt = 0; mt < 2; mt++)
        #pragma unroll
        for (int nt = 0; nt < 8; nt++)
            #pragma unroll
            for (int u = 0; u < 4; u++) acc[mt][nt][u] = 0.f;
    mma_chunk<8>(acc, a_base, wbuf[0] + w_row);
    CP_WAIT0();
    __syncthreads();               // emb + W0 reads done; W1c0 ready

    // epi L0: x = acc + b0 -> X planes
    #pragma unroll
    for (int mt = 0; mt < 2; mt++) {
        int r0 = 32 * ms + 16 * mt + g;
        #pragma unroll
        for (int nt = 0; nt < 8; nt++) {
            int j0 = 64 * ns + 8 * nt + 2 * tg;
            uint32_t off = (j0 >> 4) * 4096u + perm16(j0 & 15) * 2u;
            float bb0 = s_bias[SB_B0 + j0], bb1 = s_bias[SB_B0 + j0 + 1];
            uint16_t h0, l0, h1, l1;
            hsplit(acc[mt][nt][0] + bb0, h0, l0);
            hsplit(acc[mt][nt][1] + bb1, h1, l1);
            *(uint32_t*)(sx1 + off + r0 * 32) = (uint32_t)h0 | ((uint32_t)h1 << 16);
            *(uint32_t*)(sx2 + off + r0 * 32) = (uint32_t)l0 | ((uint32_t)l1 << 16);
            hsplit(acc[mt][nt][2] + bb0, h0, l0);
            hsplit(acc[mt][nt][3] + bb1, h1, l1);
            *(uint32_t*)(sx1 + off + (r0 + 8) * 32) = (uint32_t)h0 | ((uint32_t)h1 << 16);
            *(uint32_t*)(sx2 + off + (r0 + 8) * 32) = (uint32_t)l0 | ((uint32_t)l1 << 16);
        }
    }
    __syncthreads();

    // ================= layer 1 + fused part heads ==========================
    #pragma unroll
    for (int mt = 0; mt < 2; mt++)
        #pragma unroll
        for (int nt = 0; nt < 8; nt++)
            #pragma unroll
            for (int u = 0; u < 4; u++) acc[mt][nt][u] = 0.f;

    #pragma unroll
    for (int c = 0; c < 4; c++) {
        const uint32_t cur = wbuf[(1 + c) & 1];
        const uint32_t other = wbuf[c & 1];
        stage_async(other, (c < 3) ? g_W1[c + 1] : g_W2[0], t);

        // main chunk
        mma_chunk<8>(acc, a_base + c * 16384, cur + w_row);

        // part-c sub-GEMM: this warp handles cols [64c+16ns, +16) over its rows,
        // reading the SAME staged W1 chunk image (rows 64c+16ns+..).
        {
            float pacc[2][2][4];
            #pragma unroll
            for (int mt = 0; mt < 2; mt++)
                #pragma unroll
                for (int nt = 0; nt < 2; nt++)
                    #pragma unroll
                    for (int u = 0; u < 4; u++) pacc[mt][nt][u] = 0.f;
            uint32_t wp = cur + (uint32_t)(64 * c + 16 * ns + g) * 32 + 8 * tg;
            mma_chunk<2>(pacc, a_base + c * 16384, wp);

            float rs[2][2] = {{0.f, 0.f}, {0.f, 0.f}};
            #pragma unroll
            for (int mt = 0; mt < 2; mt++)
                #pragma unroll
                for (int nt = 0; nt < 2; nt++) {
                    int j0 = 64 * c + 16 * ns + 8 * nt + 2 * tg;
                    float bb0 = s_bias[SB_B1 + j0], bb1 = s_bias[SB_B1 + j0 + 1];
                    float wc0 = s_bias[SB_WC + c * 256 + j0];
                    float wc1 = s_bias[SB_WC + c * 256 + j0 + 1];
                    rs[mt][0] = fmaf(fmaxf(pacc[mt][nt][0] + bb0, 0.f), wc0, rs[mt][0]);
                    rs[mt][0] = fmaf(fmaxf(pacc[mt][nt][1] + bb1, 0.f), wc1, rs[mt][0]);
                    rs[mt][1] = fmaf(fmaxf(pacc[mt][nt][2] + bb0, 0.f), wc0, rs[mt][1]);
                    rs[mt][1] = fmaf(fmaxf(pacc[mt][nt][3] + bb1, 0.f), wc1, rs[mt][1]);
                }
            #pragma unroll
            for (int mt = 0; mt < 2; mt++)
                #pragma unroll
                for (int hh = 0; hh < 2; hh++) {
                    float v = rs[mt][hh];
                    v += __shfl_xor_sync(0xffffffffu, v, 1);
                    v += __shfl_xor_sync(0xffffffffu, v, 2);
                    if (tg == 0) {
                        int r = 32 * ms + 16 * mt + g + 8 * hh;
                        s_part[r * 16 + c * 4 + ns] = v;
                    }
                }
        }
        CP_WAIT0();
        __syncthreads();
    }

    // epi L1: y = relu(acc + b1) -> X planes
    #pragma unroll
    for (int mt = 0; mt < 2; mt++) {
        int r0 = 32 * ms + 16 * mt + g;
        #pragma unroll
        for (int nt = 0; nt < 8; nt++) {
            int j0 = 64 * ns + 8 * nt + 2 * tg;
            uint32_t off = (j0 >> 4) * 4096u + perm16(j0 & 15) * 2u;
            float bb0 = s_bias[SB_B1 + j0], bb1 = s_bias[SB_B1 + j0 + 1];
            uint16_t h0, l0, h1, l1;
            hsplit(fmaxf(acc[mt][nt][0] + bb0, 0.f), h0, l0);
            hsplit(fmaxf(acc[mt][nt][1] + bb1, 0.f), h1, l1);
            *(uint32_t*)(sx1 + off + r0 * 32) = (uint32_t)h0 | ((uint32_t)h1 << 16);
            *(uint32_t*)(sx2 + off + r0 * 32) = (uint32_t)l0 | ((uint32_t)l1 << 16);
            hsplit(fmaxf(acc[mt][nt][2] + bb0, 0.f), h0, l0);
            hsplit(fmaxf(acc[mt][nt][3] + bb1, 0.f), h1, l1);
            *(uint32_t*)(sx1 + off + (r0 + 8) * 32) = (uint32_t)h0 | ((uint32_t)h1 << 16);
            *(uint32_t*)(sx2 + off + (r0 + 8) * 32) = (uint32_t)l0 | ((uint32_t)l1 << 16);
        }
    }
    __syncthreads();

    // ================= layer 2 =============================================
    #pragma unroll
    for (int mt = 0; mt < 2; mt++)
        #pragma unroll
        for (int nt = 0; nt < 8; nt++)
            #pragma unroll
            for (int u = 0; u < 4; u++) acc[mt][nt][u] = 0.f;

    #pragma unroll
    for (int c = 0; c < 4; c++) {
        const uint32_t cur = wbuf[(1 + c) & 1];
        const uint32_t other = wbuf[c & 1];
        if (c < 3) stage_async(other, g_W2[c + 1], t);
        mma_chunk<8>(acc, a_base + c * 16384, cur + w_row);
        CP_WAIT0();
        __syncthreads();
    }

    // ---- occ head ----
    {
        float rs[2][2] = {{0.f, 0.f}, {0.f, 0.f}};
        #pragma unroll
        for (int mt = 0; mt < 2; mt++)
            #pragma unroll
            for (int nt = 0; nt < 8; nt++) {
                int j0 = 64 * ns + 8 * nt + 2 * tg;
                float bb0 = s_bias[SB_B2 + j0], bb1 = s_bias[SB_B2 + j0 + 1];
                float wo0 = s_bias[SB_WOCC + j0], wo1 = s_bias[SB_WOCC + j0 + 1];
                rs[mt][0] = fmaf(fmaxf(acc[mt][nt][0] + bb0, 0.f), wo0, rs[mt][0]);
                rs[mt][0] = fmaf(fmaxf(acc[mt][nt][1] + bb1, 0.f), wo1, rs[mt][0]);
                rs[mt][1] = fmaf(fmaxf(acc[mt][nt][2] + bb0, 0.f), wo0, rs[mt][1]);
                rs[mt][1] = fmaf(fmaxf(acc[mt][nt][3] + bb1, 0.f), wo1, rs[mt][1]);
            }
        #pragma unroll
        for (int mt = 0; mt < 2; mt++)
            #pragma unroll
            for (int hh = 0; hh < 2; hh++) {
                float v = rs[mt][hh];
                v += __shfl_xor_sync(0xffffffffu, v, 1);
                v += __shfl_xor_sync(0xffffffffu, v, 2);
                if (tg == 0) {
                    int r = 32 * ms + 16 * mt + g + 8 * hh;
                    s_occ[r * 4 + ns] = v;
                }
            }
    }
    __syncthreads();

    // ---- final stores ----
    if (t < 128) {
        int gm = gbase + t;
        if (gm < npts)
            out[gm] = s_occ[4 * t] + s_occ[4 * t + 1] + s_occ[4 * t + 2]
                    + s_occ[4 * t + 3] + s_bias[SB_BOCC];
    }
    {
        int m = t >> 2, p = t & 3;
        int gm = gbase + m;
        if (gm < npts)
            out[npts + gm * 4 + p] =
                s_part[m * 16 + p * 4 + 0] + s_part[m * 16 + p * 4 + 1] +
                s_part[m * 16 + p * 4 + 2] + s_part[m * 16 + p * 4 + 3] +
                s_bias[SB_BC + p];
    }
}

// ---------------------------------------------------------------------------
extern "C" void kernel_launch(void* const* d_in, const int* in_sizes, int n_in,
                              void* d_out, int out_size)
{
    const float* coords = (const float*)d_in[0];
    const float* W0   = (const float*)d_in[1];
    const float* b0   = (const float*)d_in[2];
    const float* W1   = (const float*)d_in[3];
    const float* b1   = (const float*)d_in[4];
    const float* W2   = (const float*)d_in[5];
    const float* b2   = (const float*)d_in[6];
    const float* Wocc = (const float*)d_in[7];
    const float* bocc = (const float*)d_in[8];
    const float* Wc   = (const float*)d_in[9];
    const float* bc   = (const float*)d_in[10];
    float* out = (float*)d_out;

    int npts = in_sizes[0] / 3;
    int blocks = (npts + MPB - 1) / MPB;

    prep_kernel<<<576, 256>>>(W0, W1, W2);

    cudaFuncSetAttribute(mlp3d_mma, cudaFuncAttributeMaxDynamicSharedMemorySize,
                         (int)SMEM_TOTAL);
    mlp3d_mma<<<blocks, THREADS, SMEM_TOTAL>>>(coords, b0, b1, b2, Wocc, bocc,
                                               Wc, bc, out, npts);
    (void)n_in; (void)out_size;
}

// round 8
// speedup vs baseline: 1.9722x; 1.5224x over previous
#include <cuda_runtime.h>
#include <cuda_fp16.h>
#include <math.h>
#include <stdint.h>

// ---------------------------------------------------------------------------
#define THREADS   256
#define MPB       64
// k-permutation within each 16-group: pairs (2t,2t+1,2t+8,2t+9) contiguous
__host__ __device__ __forceinline__ int perm16(int k) {
    return ((k >> 1) & 3) * 4 + (k & 1) + ((k >> 3) & 1) * 2;
}

// X smem: [ktg 16][m 64][32B] per plane; chunk stride 8192, kt stride 2048
#define X_PLANE   32768u
#define OFF_X1    0u
#define OFF_X2    32768u
#define OFF_BIAS  65536u         // 2053 floats -> 8224B
#define OFF_PART  73760u         // 64*8 floats
#define OFF_OCC   75808u         // 64*8 floats
#define SMEM_TOTAL 77856u

#define SB_B0   0
#define SB_B1   256
#define SB_B2   512
#define SB_WOCC 768
#define SB_WC   1024
#define SB_BC   2048
#define SB_BOCC 2052

// ---------------------------------------------------------------------------
// prepped fp16 weight images: per 64-k chunk [kt 4][n 256][16 halves perm16]
__device__ __align__(16) __half g_W0[16384];
__device__ __align__(16) __half g_W1[4][16384];
__device__ __align__(16) __half g_W2[4][16384];

// ---------------------------------------------------------------------------
__device__ __forceinline__ uint32_t smem_u32(const void* p) {
    uint32_t a;
    asm("{ .reg .u64 t; cvta.to.shared.u64 t, %1; cvt.u32.u64 %0, t; }" : "=r"(a) : "l"(p));
    return a;
}
__device__ __forceinline__ void lds64(uint32_t addr, uint32_t& x, uint32_t& y) {
    asm volatile("ld.shared.v2.b32 {%0,%1}, [%2];" : "=r"(x), "=r"(y) : "r"(addr));
}
__device__ __forceinline__ void mma16816(float* c, uint32_t a0, uint32_t a1,
                                         uint32_t a2, uint32_t a3,
                                         uint32_t b0, uint32_t b1) {
    asm volatile(
        "mma.sync.aligned.m16n8k16.row.col.f32.f16.f16.f32 "
        "{%0,%1,%2,%3}, {%4,%5,%6,%7}, {%8,%9}, {%0,%1,%2,%3};"
        : "+f"(c[0]), "+f"(c[1]), "+f"(c[2]), "+f"(c[3])
        : "r"(a0), "r"(a1), "r"(a2), "r"(a3), "r"(b0), "r"(b1));
}
__device__ __forceinline__ void hsplit(float v, uint16_t& h, uint16_t& l) {
    __half hh = __float2half_rn(v);
    __half ll = __float2half_rn(v - __half2float(hh));
    h = __half_as_ushort(hh);
    l = __half_as_ushort(ll);
}

// ---------------------------------------------------------------------------
__global__ void prep_kernel(const float* __restrict__ W0,
                            const float* __restrict__ W1,
                            const float* __restrict__ W2)
{
    int i = blockIdx.x * 256 + threadIdx.x;          // 147456 total
    float v; __half* d; int n, kl;
    if (i < 16384) {
        n = i >> 6; kl = i & 63;
        v = (kl < 63) ? W0[kl * 256 + n] : 0.f;
        d = g_W0;
    } else if (i < 16384 + 65536) {
        int t2 = i - 16384;
        int c = t2 >> 14; n = (t2 >> 6) & 255; kl = t2 & 63;
        v = W1[(c * 64 + kl) * 256 + n];
        d = g_W1[c];
    } else {
        int t2 = i - 16384 - 65536;
        if (t2 >= 65536) return;
        int c = t2 >> 14; n = (t2 >> 6) & 255; kl = t2 & 63;
        v = W2[(c * 64 + kl) * 256 + n];
        d = g_W2[c];
    }
    int kt = kl >> 4, pp = perm16(kl & 15);
    d[kt * 4096 + n * 16 + pp] = __float2half_rn(v);
}

// ---------------------------------------------------------------------------
// one 64-k chunk: A from smem (64m), W via direct LDG (32n), 2-term fp16
// a_base: chunk-resolved smem addr (row g, +8tg). wimg: chunk image.
__device__ __forceinline__ void mma_chunk(float acc[4][4][4],
                                          uint32_t a_base,
                                          const __half* __restrict__ wimg,
                                          int ns, int g, int tg)
{
    const char* wp = (const char*)wimg + (uint32_t)(32 * ns + g) * 32 + 8 * tg;
    uint2 wc[4], wn[4];
    #pragma unroll
    for (int nt = 0; nt < 4; nt++) wc[nt] = *(const uint2*)(wp + nt * 256);
    #pragma unroll
    for (int kt = 0; kt < 4; kt++) {
        if (kt < 3) {
            #pragma unroll
            for (int nt = 0; nt < 4; nt++)
                wn[nt] = *(const uint2*)(wp + (kt + 1) * 8192 + nt * 256);
        }
        #pragma unroll
        for (int mt = 0; mt < 4; mt++) {
            uint32_t ab = a_base + kt * 2048 + mt * 512;
            uint32_t ah0, ah2, ah1, ah3, al0, al2, al1, al3;
            lds64(ab,                 ah0, ah2);
            lds64(ab + 256,           ah1, ah3);
            lds64(ab + X_PLANE,       al0, al2);
            lds64(ab + 256 + X_PLANE, al1, al3);
            #pragma unroll
            for (int nt = 0; nt < 4; nt++) {
                mma16816(acc[mt][nt], ah0, ah1, ah2, ah3, wc[nt].x, wc[nt].y);
                mma16816(acc[mt][nt], al0, al1, al2, al3, wc[nt].x, wc[nt].y);
            }
        }
        #pragma unroll
        for (int nt = 0; nt < 4; nt++) wc[nt] = wn[nt];
    }
}

// ---------------------------------------------------------------------------
__global__ __launch_bounds__(THREADS, 2)
void mlp3d_mma(const float* __restrict__ coords,
               const float* __restrict__ b0, const float* __restrict__ b1,
               const float* __restrict__ b2,
               const float* __restrict__ Wocc, const float* __restrict__ bocc,
               const float* __restrict__ Wc, const float* __restrict__ bc,
               float* __restrict__ out, int npts)
{
    extern __shared__ char sm[];
    char*  sx1 = sm + OFF_X1;
    char*  sx2 = sm + OFF_X2;
    float* s_bias = (float*)(sm + OFF_BIAS);
    float* s_part = (float*)(sm + OFF_PART);   // [m 64][ns 8]
    float* s_occ  = (float*)(sm + OFF_OCC);    // [m 64][ns 8]
    const uint32_t smb = smem_u32(sm);

    const int t = threadIdx.x;
    const int ns = t >> 5, lane = t & 31;      // warp = n-strip (32 cols)
    const int p = ns >> 1;                     // part owned by this warp pair
    const int g = lane >> 2, tg = lane & 3;
    const int gbase = blockIdx.x * MPB;

    const uint32_t a_rt = smb + OFF_X1 + (uint32_t)g * 32 + 8 * tg;

    // ---- biases / heads -> smem ----
    for (int i = t; i < 2053; i += THREADS) {
        float v;
        if      (i < 256)  v = b0[i];
        else if (i < 512)  v = b1[i - 256];
        else if (i < 768)  v = b2[i - 512];
        else if (i < 1024) v = Wocc[i - 768];
        else if (i < 2048) v = Wc[i - 1024];
        else if (i < 2052) v = bc[i - 2048];
        else               v = bocc[0];
        s_bias[i] = v;
    }

    // ---- embedding -> X chunk 0 (64 pts x 64 k), hi/lo planes ----
    if (t < 192) {
        int pt = t & 63, d = t >> 6;
        int eg = gbase + pt;
        float v = (eg < npts) ? coords[eg * 3 + d] : 0.f;
        uint16_t hh, ll;
        hsplit(v, hh, ll);
        uint32_t off = (uint32_t)(d >> 4) * 2048u + pt * 32u + perm16(d & 15) * 2u;
        *(uint16_t*)(sx1 + off) = hh; *(uint16_t*)(sx2 + off) = ll;
        float f = 1.f;
        #pragma unroll
        for (int fr = 0; fr < 10; fr++) {
            float sv, cv;
            sincosf(v * f, &sv, &cv);
            int ks = 3 + fr * 6 + d, kc = ks + 3;
            uint32_t os = (uint32_t)(ks >> 4) * 2048u + pt * 32u + perm16(ks & 15) * 2u;
            uint32_t oc = (uint32_t)(kc >> 4) * 2048u + pt * 32u + perm16(kc & 15) * 2u;
            hsplit(sv, hh, ll);
            *(uint16_t*)(sx1 + os) = hh; *(uint16_t*)(sx2 + os) = ll;
            hsplit(cv, hh, ll);
            *(uint16_t*)(sx1 + oc) = hh; *(uint16_t*)(sx2 + oc) = ll;
            f *= 2.f;
        }
    }
    if (t < 64) {   // pad k=63
        uint32_t off = 3u * 2048u + t * 32u + 15 * 2u;
        *(uint16_t*)(sx1 + off) = 0;
        *(uint16_t*)(sx2 + off) = 0;
    }
    __syncthreads();

    float acc[4][4][4];

    // ================= layer 0 : x = emb @ W0 + b0 ==========================
    #pragma unroll
    for (int mt = 0; mt < 4; mt++)
        #pragma unroll
        for (int nt = 0; nt < 4; nt++)
            #pragma unroll
            for (int u = 0; u < 4; u++) acc[mt][nt][u] = 0.f;
    mma_chunk(acc, a_rt, g_W0, ns, g, tg);
    __syncthreads();               // emb reads done

    // epi L0 -> X (all 4 chunks)
    #pragma unroll
    for (int mt = 0; mt < 4; mt++) {
        int r0 = 16 * mt + g;
        #pragma unroll
        for (int nt = 0; nt < 4; nt++) {
            int j0 = 32 * ns + 8 * nt + 2 * tg;
            uint32_t off = (uint32_t)(j0 >> 4) * 2048u + perm16(j0 & 15) * 2u;
            float bb0 = s_bias[SB_B0 + j0], bb1 = s_bias[SB_B0 + j0 + 1];
            uint16_t h0, l0, h1, l1;
            hsplit(acc[mt][nt][0] + bb0, h0, l0);
            hsplit(acc[mt][nt][1] + bb1, h1, l1);
            *(uint32_t*)(sx1 + off + r0 * 32) = (uint32_t)h0 | ((uint32_t)h1 << 16);
            *(uint32_t*)(sx2 + off + r0 * 32) = (uint32_t)l0 | ((uint32_t)l1 << 16);
            hsplit(acc[mt][nt][2] + bb0, h0, l0);
            hsplit(acc[mt][nt][3] + bb1, h1, l1);
            *(uint32_t*)(sx1 + off + (r0 + 8) * 32) = (uint32_t)h0 | ((uint32_t)h1 << 16);
            *(uint32_t*)(sx2 + off + (r0 + 8) * 32) = (uint32_t)l0 | ((uint32_t)l1 << 16);
        }
    }
    __syncthreads();

    // ================= layer 1 (chunks staggered; part head after 1st) =====
    #pragma unroll
    for (int mt = 0; mt < 4; mt++)
        #pragma unroll
        for (int nt = 0; nt < 4; nt++)
            #pragma unroll
            for (int u = 0; u < 4; u++) acc[mt][nt][u] = 0.f;

    #pragma unroll
    for (int i = 0; i < 4; i++) {
        int c = (p + i) & 3;
        mma_chunk(acc, a_rt + c * 8192, g_W1[c], ns, g, tg);
        if (i == 0) {
            // acc == part-p pre-activation (chunk p only) for this warp's cols
            float pr[4][2];
            #pragma unroll
            for (int mt = 0; mt < 4; mt++) { pr[mt][0] = 0.f; pr[mt][1] = 0.f; }
            #pragma unroll
            for (int mt = 0; mt < 4; mt++)
                #pragma unroll
                for (int nt = 0; nt < 4; nt++) {
                    int j0 = 32 * ns + 8 * nt + 2 * tg;
                    float bb0 = s_bias[SB_B1 + j0], bb1 = s_bias[SB_B1 + j0 + 1];
                    float wc0 = s_bias[SB_WC + p * 256 + j0];
                    float wc1 = s_bias[SB_WC + p * 256 + j0 + 1];
                    pr[mt][0] = fmaf(fmaxf(acc[mt][nt][0] + bb0, 0.f), wc0, pr[mt][0]);
                    pr[mt][0] = fmaf(fmaxf(acc[mt][nt][1] + bb1, 0.f), wc1, pr[mt][0]);
                    pr[mt][1] = fmaf(fmaxf(acc[mt][nt][2] + bb0, 0.f), wc0, pr[mt][1]);
                    pr[mt][1] = fmaf(fmaxf(acc[mt][nt][3] + bb1, 0.f), wc1, pr[mt][1]);
                }
            #pragma unroll
            for (int mt = 0; mt < 4; mt++)
                #pragma unroll
                for (int hh = 0; hh < 2; hh++) {
                    float v = pr[mt][hh];
                    v += __shfl_xor_sync(0xffffffffu, v, 1);
                    v += __shfl_xor_sync(0xffffffffu, v, 2);
                    if (tg == 0)
                        s_part[(16 * mt + g + 8 * hh) * 8 + ns] = v;
                }
        }
    }
    __syncthreads();               // all X reads done

    // epi L1: y = relu(acc + b1) -> X
    #pragma unroll
    for (int mt = 0; mt < 4; mt++) {
        int r0 = 16 * mt + g;
        #pragma unroll
        for (int nt = 0; nt < 4; nt++) {
            int j0 = 32 * ns + 8 * nt + 2 * tg;
            uint32_t off = (uint32_t)(j0 >> 4) * 2048u + perm16(j0 & 15) * 2u;
            float bb0 = s_bias[SB_B1 + j0], bb1 = s_bias[SB_B1 + j0 + 1];
            uint16_t h0, l0, h1, l1;
            hsplit(fmaxf(acc[mt][nt][0] + bb0, 0.f), h0, l0);
            hsplit(fmaxf(acc[mt][nt][1] + bb1, 0.f), h1, l1);
            *(uint32_t*)(sx1 + off + r0 * 32) = (uint32_t)h0 | ((uint32_t)h1 << 16);
            *(uint32_t*)(sx2 + off + r0 * 32) = (uint32_t)l0 | ((uint32_t)l1 << 16);
            hsplit(fmaxf(acc[mt][nt][2] + bb0, 0.f), h0, l0);
            hsplit(fmaxf(acc[mt][nt][3] + bb1, 0.f), h1, l1);
            *(uint32_t*)(sx1 + off + (r0 + 8) * 32) = (uint32_t)h0 | ((uint32_t)h1 << 16);
            *(uint32_t*)(sx2 + off + (r0 + 8) * 32) = (uint32_t)l0 | ((uint32_t)l1 << 16);
        }
    }
    __syncthreads();

    // ================= layer 2 =============================================
    #pragma unroll
    for (int mt = 0; mt < 4; mt++)
        #pragma unroll
        for (int nt = 0; nt < 4; nt++)
            #pragma unroll
            for (int u = 0; u < 4; u++) acc[mt][nt][u] = 0.f;

    #pragma unroll
    for (int i = 0; i < 4; i++) {
        int c = (p + i) & 3;
        mma_chunk(acc, a_rt + c * 8192, g_W2[c], ns, g, tg);
    }

    // ---- occ head ----
    {
        float pr[4][2];
        #pragma unroll
        for (int mt = 0; mt < 4; mt++) { pr[mt][0] = 0.f; pr[mt][1] = 0.f; }
        #pragma unroll
        for (int mt = 0; mt < 4; mt++)
            #pragma unroll
            for (int nt = 0; nt < 4; nt++) {
                int j0 = 32 * ns + 8 * nt + 2 * tg;
                float bb0 = s_bias[SB_B2 + j0], bb1 = s_bias[SB_B2 + j0 + 1];
                float wo0 = s_bias[SB_WOCC + j0], wo1 = s_bias[SB_WOCC + j0 + 1];
                pr[mt][0] = fmaf(fmaxf(acc[mt][nt][0] + bb0, 0.f), wo0, pr[mt][0]);
                pr[mt][0] = fmaf(fmaxf(acc[mt][nt][1] + bb1, 0.f), wo1, pr[mt][0]);
                pr[mt][1] = fmaf(fmaxf(acc[mt][nt][2] + bb0, 0.f), wo0, pr[mt][1]);
                pr[mt][1] = fmaf(fmaxf(acc[mt][nt][3] + bb1, 0.f), wo1, pr[mt][1]);
            }
        #pragma unroll
        for (int mt = 0; mt < 4; mt++)
            #pragma unroll
            for (int hh = 0; hh < 2; hh++) {
                float v = pr[mt][hh];
                v += __shfl_xor_sync(0xffffffffu, v, 1);
                v += __shfl_xor_sync(0xffffffffu, v, 2);
                if (tg == 0)
                    s_occ[(16 * mt + g + 8 * hh) * 8 + ns] = v;
            }
    }
    __syncthreads();

    // ---- final stores ----
    if (t < 64) {
        int gm = gbase + t;
        if (gm < npts) {
            float s = s_bias[SB_BOCC];
            #pragma unroll
            for (int w = 0; w < 8; w++) s += s_occ[t * 8 + w];
            out[gm] = s;
        }
    }
    {
        int m = t >> 2, pp = t & 3;
        int gm = gbase + m;
        if (gm < npts)
            out[npts + gm * 4 + pp] =
                s_part[m * 8 + 2 * pp] + s_part[m * 8 + 2 * pp + 1] +
                s_bias[SB_BC + pp];
    }
}

// ---------------------------------------------------------------------------
extern "C" void kernel_launch(void* const* d_in, const int* in_sizes, int n_in,
                              void* d_out, int out_size)
{
    const float* coords = (const float*)d_in[0];
    const float* W0   = (const float*)d_in[1];
    const float* b0   = (const float*)d_in[2];
    const float* W1   = (const float*)d_in[3];
    const float* b1   = (const float*)d_in[4];
    const float* W2   = (const float*)d_in[5];
    const float* b2   = (const float*)d_in[6];
    const float* Wocc = (const float*)d_in[7];
    const float* bocc = (const float*)d_in[8];
    const float* Wc   = (const float*)d_in[9];
    const float* bc   = (const float*)d_in[10];
    float* out = (float*)d_out;

    int npts = in_sizes[0] / 3;
    int blocks = (npts + MPB - 1) / MPB;

    prep_kernel<<<576, 256>>>(W0, W1, W2);

    cudaFuncSetAttribute(mlp3d_mma, cudaFuncAttributeMaxDynamicSharedMemorySize,
                         (int)SMEM_TOTAL);
    mlp3d_mma<<<blocks, THREADS, SMEM_TOTAL>>>(coords, b0, b1, b2, Wocc, bocc,
                                               Wc, bc, out, npts);
    (void)n_in; (void)out_size;
}